// round 4
// baseline (speedup 1.0000x reference)
#include <cuda_runtime.h>

#define NB 32
#define NA 8400
#define NC 80
#define NM 64
#define KTOP 13
#define FEPS 1e-9f
#define CAP 2048
#define NBIN 64
#define MAXPOS (NB * NM * KTOP)
#define APB (NA / 4)              /* 2100 anchor-groups per batch */

// Persistent scratch (device globals)
__device__ unsigned long long g_bits[NB * NA];
__device__ float              g_maxmet[NB * NM];
__device__ float              g_maxiou[NB * NM];
__device__ float2             g_apb[NA];
__device__ int                g_aidx[NA];
__device__ int                g_hist[NBIN];
__device__ int                g_binstart[NBIN + 1];
__device__ int                g_binoff[NBIN];
__device__ int                g_poscnt;
__device__ int2               g_poslist[MAXPOS];

__device__ __forceinline__ float iou_fn(float gx1, float gy1, float gx2, float gy2,
                                        float garea, float4 p) {
    float ix1 = fmaxf(gx1, p.x), iy1 = fmaxf(gy1, p.y);
    float ix2 = fminf(gx2, p.z), iy2 = fminf(gy2, p.w);
    float ov  = fmaxf(ix2 - ix1, 0.f) * fmaxf(iy2 - iy1, 0.f);
    float pa  = fmaxf(p.z - p.x, 0.f) * fmaxf(p.w - p.y, 0.f);
    return ov / (garea + pa - ov + FEPS);
}

__device__ __forceinline__ int ybin(float y) {
    int b = (int)(y * (NBIN / 640.0f));
    return min(max(b, 0), NBIN - 1);
}

// ---------------------------------------------------------------------------
__global__ void k_init() {
    int i = blockIdx.x * blockDim.x + threadIdx.x;
    if (i < NB * NA) g_bits[i] = 0ull;
    if (i < NB * NM) { g_maxmet[i] = 0.f; g_maxiou[i] = 0.f; }
    if (i < NBIN) g_hist[i] = 0;
    if (i == 0) g_poscnt = 0;
}

// ---------------------------------------------------------------------------
// Parallel counting sort of anchors into y-bins (3 tiny kernels)
// ---------------------------------------------------------------------------
__global__ __launch_bounds__(256)
void k_hist(const float* __restrict__ ap) {
    __shared__ int lh[NBIN];
    int t = threadIdx.x;
    if (t < NBIN) lh[t] = 0;
    __syncthreads();
    int a = blockIdx.x * 256 + t;
    if (a < NA) atomicAdd(&lh[ybin(((const float2*)ap)[a].y)], 1);
    __syncthreads();
    if (t < NBIN && lh[t]) atomicAdd(&g_hist[t], lh[t]);
}

__global__ void k_scan() {
    if (threadIdx.x == 0) {
        int acc = 0;
        for (int i = 0; i < NBIN; i++) {
            g_binstart[i] = acc; g_binoff[i] = acc; acc += g_hist[i];
        }
        g_binstart[NBIN] = acc;
    }
}

__global__ __launch_bounds__(256)
void k_scatter(const float* __restrict__ ap) {
    __shared__ int lh[NBIN], lb[NBIN];
    int t = threadIdx.x;
    if (t < NBIN) lh[t] = 0;
    __syncthreads();
    int a = blockIdx.x * 256 + t;
    float2 c = make_float2(0.f, 0.f);
    int bin = -1;
    if (a < NA) { c = ((const float2*)ap)[a]; bin = ybin(c.y); atomicAdd(&lh[bin], 1); }
    __syncthreads();
    if (t < NBIN) { lb[t] = lh[t] ? atomicAdd(&g_binoff[t], lh[t]) : 0; lh[t] = 0; }
    __syncthreads();
    if (a < NA) {
        int pos = lb[bin] + atomicAdd(&lh[bin], 1);
        g_apb[pos]  = c;
        g_aidx[pos] = a;
    }
}

// ---------------------------------------------------------------------------
// Kernel: per (b,m) — scan y-bin window, compact candidates as unique packed
// keys (value desc, index asc == lax.top_k order), select top-13, scatter bits
// ---------------------------------------------------------------------------
__global__ __launch_bounds__(256)
void k_topk(const float* __restrict__ ps,
            const float* __restrict__ pb,
            const int*   __restrict__ gl,
            const float* __restrict__ gb,
            const float* __restrict__ pm)
{
    int bm = blockIdx.x;
    if (pm[bm] == 0.f) return;
    int b = bm >> 6, m = bm & 63;

    __shared__ unsigned long long keys[CAP];
    __shared__ unsigned long long wred[8];
    __shared__ unsigned long long s_kprev;
    __shared__ int s_cnt;

    int t = threadIdx.x, lane = t & 31;
    if (t == 0) s_cnt = 0;
    __syncthreads();

    float gx1 = gb[bm * 4 + 0], gy1 = gb[bm * 4 + 1];
    float gx2 = gb[bm * 4 + 2], gy2 = gb[bm * 4 + 3];
    float garea = fmaxf(gx2 - gx1, 0.f) * fmaxf(gy2 - gy1, 0.f);
    int lab = gl[bm];

    const float4* pbv = (const float4*)pb + (size_t)b * NA;
    const float*  psb = ps + (size_t)b * NA * NC + lab;

    int lo = g_binstart[ybin(gy1)];
    int hi = g_binstart[ybin(gy2) + 1];

    for (int base = lo; base < hi; base += 256) {
        int i = base + t;
        bool inb = i < hi;
        float d = -1.f;
        int a = 0;
        if (inb) {
            float2 c = g_apb[i];
            a = g_aidx[i];
            d = fminf(fminf(c.x - gx1, c.y - gy1), fminf(gx2 - c.x, gy2 - c.y));
        }
        bool pred = inb && (d > FEPS);
        unsigned act = __ballot_sync(0xffffffffu, pred);
        if (pred) {
            float4 p   = pbv[a];
            float  iou = iou_fn(gx1, gy1, gx2, gy2, garea, p);
            float  cls = __ldg(psb + (size_t)a * NC);
            float  i2  = iou * iou;
            float  met = cls * (i2 * i2 * i2);
            unsigned long long key =
                ((unsigned long long)__float_as_uint(met) << 32) | (unsigned)(NA - a);
            int rank   = __popc(act & ((1u << lane) - 1u));
            int leader = __ffs(act) - 1;
            int pos;
            if (lane == leader) pos = atomicAdd(&s_cnt, __popc(act));
            pos = __shfl_sync(act, pos, leader) + rank;
            if (pos < CAP) keys[pos] = key;
        }
    }
    __syncthreads();
    int n = min(s_cnt, CAP);

    unsigned long long kprev = 0xFFFFFFFFFFFFFFFFull;
    for (int k = 0; k < KTOP; k++) {
        unsigned long long best = 0ull;
        for (int i = t; i < n; i += 256) {
            unsigned long long kk = keys[i];
            if (kk < kprev && kk > best) best = kk;
        }
        #pragma unroll
        for (int s = 16; s; s >>= 1) {
            unsigned long long o = __shfl_down_sync(0xffffffffu, best, s);
            if (o > best) best = o;
        }
        if (lane == 0) wred[t >> 5] = best;
        __syncthreads();
        if (t < 32) {
            unsigned long long b2 = (t < 8) ? wred[t] : 0ull;
            #pragma unroll
            for (int s = 4; s; s >>= 1) {
                unsigned long long o = __shfl_down_sync(0xffffffffu, b2, s);
                if (o > b2) b2 = o;
            }
            if (t == 0) {
                s_kprev = b2;
                if (b2) {
                    int aidx = NA - (int)(b2 & 0xffffffffu);
                    atomicOr(&g_bits[(size_t)b * NA + aidx], 1ull << m);
                }
            }
        }
        __syncthreads();
        kprev = s_kprev;
        if (!kprev) break;
    }
}

// ---------------------------------------------------------------------------
// Kernel: 4 anchors per thread — resolve multi-assignment, emit labels/bboxes,
// per-(b,m) maxima, warp-aggregated positive-list append. No barriers.
// ---------------------------------------------------------------------------
__global__ __launch_bounds__(256)
void k_assign(const float* __restrict__ ps,
              const float* __restrict__ pb,
              const int*   __restrict__ gl,
              const float* __restrict__ gb,
              const int*   __restrict__ bgp,
              float* __restrict__ out_lab,   // [B,A]
              float* __restrict__ out_box)   // [B,A,4]
{
    int tid  = blockIdx.x * 256 + threadIdx.x;
    int lane = threadIdx.x & 31;
    bool live = tid < NB * APB;

    unsigned long long bits[4] = {0ull, 0ull, 0ull, 0ull};
    size_t base = 0;
    int b = 0;
    if (live) {
        b = tid / APB;
        int a0 = (tid - b * APB) * 4;
        base = (size_t)b * NA + a0;
        ulonglong2 w0 = *(const ulonglong2*)&g_bits[base];
        ulonglong2 w1 = *(const ulonglong2*)&g_bits[base + 2];
        bits[0] = w0.x; bits[1] = w0.y; bits[2] = w1.x; bits[3] = w1.y;
    }

    const float4* gbv = (const float4*)gb + b * NM;
    float4 bgbox = live ? __ldg(gbv) : make_float4(0.f, 0.f, 0.f, 0.f);
    float  bgl   = live ? (float)*bgp : 0.f;

    int   mfin[4];
    float lab4[4];
    float4 box4[4];
    int cnt = 0;

    #pragma unroll
    for (int j = 0; j < 4; j++) {
        mfin[j] = -1; lab4[j] = bgl; box4[j] = bgbox;
        if (!bits[j]) continue;
        int m;
        if (__popcll(bits[j]) > 1) {
            float4 p = __ldg((const float4*)pb + base + j);
            float bestv = -1.f; int bestm = 0;
            for (int mm = 0; mm < NM; mm++) {
                float4 g = __ldg(gbv + mm);
                float ga = fmaxf(g.z - g.x, 0.f) * fmaxf(g.w - g.y, 0.f);
                float iou = iou_fn(g.x, g.y, g.z, g.w, ga, p);
                if (iou > bestv) { bestv = iou; bestm = mm; }
            }
            m = bestm;
        } else {
            m = __ffsll((long long)bits[j]) - 1;
        }
        mfin[j] = m;
        int lab = __ldg(&gl[b * NM + m]);
        lab4[j] = (float)lab;
        float4 g = __ldg(gbv + m);
        box4[j] = g;
        // per-(b,m) maxima
        float4 p = __ldg((const float4*)pb + base + j);
        float ga = fmaxf(g.z - g.x, 0.f) * fmaxf(g.w - g.y, 0.f);
        float iou = iou_fn(g.x, g.y, g.z, g.w, ga, p);
        float cls = __ldg(&ps[(base + j) * NC + lab]);
        float i2 = iou * iou;
        float align = cls * (i2 * i2 * i2);
        atomicMax((int*)&g_maxmet[b * NM + m], __float_as_int(align));
        atomicMax((int*)&g_maxiou[b * NM + m], __float_as_int(iou));
        cnt++;
    }

    if (live) {
        *(float4*)&out_lab[base] = make_float4(lab4[0], lab4[1], lab4[2], lab4[3]);
        float4* ob = (float4*)out_box + base;
        ob[0] = box4[0]; ob[1] = box4[1]; ob[2] = box4[2]; ob[3] = box4[3];
    }

    // warp-aggregated poslist append
    int pre = cnt;
    #pragma unroll
    for (int s = 1; s < 32; s <<= 1) {
        int o = __shfl_up_sync(0xffffffffu, pre, s);
        if (lane >= s) pre += o;
    }
    int total = __shfl_sync(0xffffffffu, pre, 31);
    int ex = pre - cnt;
    int gbase = 0;
    if (lane == 31 && total) gbase = atomicAdd(&g_poscnt, total);
    gbase = __shfl_sync(0xffffffffu, gbase, 31);
    if (cnt) {
        int w = 0;
        #pragma unroll
        for (int j = 0; j < 4; j++)
            if (mfin[j] >= 0) g_poslist[gbase + ex + (w++)] = make_int2((int)(base + j), mfin[j]);
    }
}

// ---------------------------------------------------------------------------
// Kernel: over compact positive list — normalized score scatter
// ---------------------------------------------------------------------------
__global__ __launch_bounds__(256)
void k_scores(const float* __restrict__ ps,
              const float* __restrict__ pb,
              const int*   __restrict__ gl,
              const float* __restrict__ gb,
              const int*   __restrict__ bgp,
              float* __restrict__ out_sc)    // [B,A,C]
{
    int tid = blockIdx.x * 256 + threadIdx.x;
    if (tid >= g_poscnt) return;
    int2 e = g_poslist[tid];
    size_t ia = (size_t)(unsigned)e.x;
    int m = e.y;
    int b = (int)(ia / NA);
    int bmi = b * NM + m;

    float4 p = __ldg((const float4*)pb + ia);
    float4 g = __ldg((const float4*)gb + bmi);
    float ga = fmaxf(g.z - g.x, 0.f) * fmaxf(g.w - g.y, 0.f);
    float iou = iou_fn(g.x, g.y, g.z, g.w, ga, p);
    int lab = __ldg(&gl[bmi]);
    float cls = __ldg(&ps[ia * NC + lab]);
    float i2 = iou * iou;
    float align = cls * (i2 * i2 * i2);
    float factor = align / (g_maxmet[bmi] + FEPS) * g_maxiou[bmi];

    int bg = *bgp;
    int col = (lab < bg) ? lab : (lab - 1);
    out_sc[ia * NC + col] = factor;
}

// ---------------------------------------------------------------------------
extern "C" void kernel_launch(void* const* d_in, const int* in_sizes, int n_in,
                              void* d_out, int out_size) {
    const float* ps  = (const float*)d_in[0];
    const float* pb  = (const float*)d_in[1];
    const float* ap  = (const float*)d_in[2];
    const int*   gl  = (const int*)  d_in[3];
    const float* gb  = (const float*)d_in[4];
    const float* pm  = (const float*)d_in[5];
    const int*   bgp = (const int*)  d_in[6];

    float* out      = (float*)d_out;
    float* out_lab  = out;
    float* out_box  = out + (size_t)NB * NA;
    float* out_sc   = out + (size_t)NB * NA * 5;

    static cudaStream_t s2 = nullptr;
    static cudaEvent_t ev_fork = nullptr, ev_join = nullptr;
    if (!s2) {
        cudaStreamCreateWithFlags(&s2, cudaStreamNonBlocking);
        cudaEventCreateWithFlags(&ev_fork, cudaEventDisableTiming);
        cudaEventCreateWithFlags(&ev_join, cudaEventDisableTiming);
    }

    // Fork: 86 MB memset overlaps everything up to k_scores
    cudaEventRecord(ev_fork, 0);
    cudaStreamWaitEvent(s2, ev_fork, 0);
    cudaMemsetAsync(out_sc, 0, (size_t)NB * NA * NC * sizeof(float), s2);
    cudaEventRecord(ev_join, s2);

    k_init<<<(NB * NA + 255) / 256, 256>>>();
    int ab = (NA + 255) / 256;
    k_hist<<<ab, 256>>>(ap);
    k_scan<<<1, 32>>>();
    k_scatter<<<ab, 256>>>(ap);
    k_topk<<<NB * NM, 256>>>(ps, pb, gl, gb, pm);
    k_assign<<<(NB * APB + 255) / 256, 256>>>(ps, pb, gl, gb, bgp, out_lab, out_box);

    cudaStreamWaitEvent(0, ev_join, 0);
    k_scores<<<(MAXPOS + 255) / 256, 256>>>(ps, pb, gl, gb, bgp, out_sc);
}